// round 16
// baseline (speedup 1.0000x reference)
#include <cuda_runtime.h>
#include <math_constants.h>
#include <cstdint>

// Problem constants (fixed by setup_inputs).
constexpr int B = 4, C = 3, H = 1080, W = 1920;
constexpr int PAD = 8;                 // generous pad: window loads never go OOB
constexpr int Hp = H + 2 * PAD;        // 1096
constexpr int Wp = W + 2 * PAD;        // 1936 (divisible by 4)
constexpr float ALPHA = 0.1f;

constexpr size_t PLANE = (size_t)B * Hp * Wp;   // texel positions (padded)
constexpr unsigned Wpu = (unsigned)Wp;

// 4-phase shifted replicas (quad loads): texel lin of copy c lives at
// c*STRIDE + lin + c -> any 4-texel window is 16B-aligned in exactly one copy.
constexpr size_t STRIDE = PLANE + 32;           // slack for copy-shift overflow
__device__ __align__(16) unsigned g_h4[4 * STRIDE];

// Pair replica: P[y][x] = { t[y-1][x], t[y-1][x+1], t[y+2][x], t[y+2][x+1] }.
__device__ __align__(16) uint4 g_P[PLANE];

// mv bounding box, order-preserving-encoded {min x, max x, min y, max y}.
// Statically initialized; the atomic min/max fixpoint is identical across
// graph replays for identical mv, so no reset kernel is needed.
__device__ unsigned g_bbox[4] = { 0xFFFFFFFFu, 0u, 0xFFFFFFFFu, 0u };

struct f3 { float x, y, z; };

// Magic-number decode: (1 + r/2048, 1 + g/2048, 1 + b/1024); SHF+LOP3, no I2F.
__device__ __forceinline__ f3 dec(unsigned q) {
    unsigned r = ((q << 12) & 0x007FF000u) | 0x3F800000u;
    unsigned g = ((q << 1)  & 0x007FF000u) | 0x3F800000u;
    unsigned b = ((q >> 9)  & 0x007FE000u) | 0x3F800000u;
    return { __uint_as_float(r), __uint_as_float(g), __uint_as_float(b) };
}
__device__ __forceinline__ void fma3(f3& acc, const f3& v, float w) {
    acc.x = fmaf(v.x, w, acc.x);
    acc.y = fmaf(v.y, w, acc.y);
    acc.z = fmaf(v.z, w, acc.z);
}

// Order-preserving float <-> uint encoding (monotone increasing).
__device__ __forceinline__ unsigned enc_ord(float f) {
    unsigned u = __float_as_uint(f);
    return (u & 0x80000000u) ? ~u : (u | 0x80000000u);
}
__device__ __forceinline__ float dec_ord(unsigned e) {
    return __uint_as_float((e & 0x80000000u) ? (e ^ 0x80000000u) : ~e);
}

// Clamped tap-origin bbox from the mv float bbox (monotone map -> exact bound).
__device__ __forceinline__ void bbox_kxy(int& kxmin, int& kxmax, int& kymin, int& kymax) {
    float gx0 = dec_ord(g_bbox[0]), gx1 = dec_ord(g_bbox[1]);
    float gy0 = dec_ord(g_bbox[2]), gy1 = dec_ord(g_bbox[3]);
    kxmin = min(max((int)floorf((gx0 + 1.0f) * 0.5f * (float)W - 0.5f), -2), W - 1);
    kxmax = min(max((int)floorf((gx1 + 1.0f) * 0.5f * (float)W - 0.5f), -2), W - 1);
    kymin = min(max((int)floorf((gy0 + 1.0f) * 0.5f * (float)H - 0.5f), -2), H - 1);
    kymax = min(max((int)floorf((gy1 + 1.0f) * 0.5f * (float)H - 0.5f), -2), H - 1);
}

// ---------------------------------------------------------------------------
// bbox over mv: 1800 blocks x 256 thr x 9 float4 (= exactly B*H*W*2 floats).
__global__ __launch_bounds__(256) void bbox_kernel(const float* __restrict__ mv) {
    const float4* m4 = (const float4*)mv;
    const unsigned base = blockIdx.x * 2304u + threadIdx.x;

    float mnx =  CUDART_INF_F, mxx = -CUDART_INF_F;
    float mny =  CUDART_INF_F, mxy = -CUDART_INF_F;
    #pragma unroll
    for (int k = 0; k < 9; k++) {
        float4 v = __ldg(m4 + base + k * 256u);
        mnx = fminf(mnx, fminf(v.x, v.z));  mxx = fmaxf(mxx, fmaxf(v.x, v.z));
        mny = fminf(mny, fminf(v.y, v.w));  mxy = fmaxf(mxy, fmaxf(v.y, v.w));
    }
    #pragma unroll
    for (int off = 16; off; off >>= 1) {
        mnx = fminf(mnx, __shfl_xor_sync(0xFFFFFFFFu, mnx, off));
        mxx = fmaxf(mxx, __shfl_xor_sync(0xFFFFFFFFu, mxx, off));
        mny = fminf(mny, __shfl_xor_sync(0xFFFFFFFFu, mny, off));
        mxy = fmaxf(mxy, __shfl_xor_sync(0xFFFFFFFFu, mxy, off));
    }
    __shared__ float s[4][8];
    int wid = threadIdx.x >> 5;
    if ((threadIdx.x & 31) == 0) {
        s[0][wid] = mnx; s[1][wid] = mxx; s[2][wid] = mny; s[3][wid] = mxy;
    }
    __syncthreads();
    if (threadIdx.x == 0) {
        #pragma unroll
        for (int wv = 1; wv < 8; wv++) {
            mnx = fminf(mnx, s[0][wv]);  mxx = fmaxf(mxx, s[1][wv]);
            mny = fminf(mny, s[2][wv]);  mxy = fmaxf(mxy, s[3][wv]);
        }
        atomicMin(&g_bbox[0], enc_ord(mnx));
        atomicMax(&g_bbox[1], enc_ord(mxx));
        atomicMin(&g_bbox[2], enc_ord(mny));
        atomicMax(&g_bbox[3], enc_ord(mxy));
    }
}

// ---------------------------------------------------------------------------
// packF: fused region pack (4 phase copies + pair replica), reads hist direct.
// ---------------------------------------------------------------------------
__device__ __forceinline__ unsigned quant3(float r, float g, float b) {
    return __float2uint_rn(r * 2047.0f)
         | (__float2uint_rn(g * 2047.0f) << 11)
         | (__float2uint_rn(b * 1023.0f) << 22);
}

template <int N>
__device__ __forceinline__ void qrow(const float* __restrict__ hb, int xu, int yu,
                                     unsigned* t) {
    if (yu < 0 || yu >= H) {
        #pragma unroll
        for (int i = 0; i < N; i++) t[i] = 0u;
        return;
    }
    const unsigned HW = (unsigned)(H * W);
    const float* r0 = hb + (unsigned)yu * (unsigned)W;
    if (xu >= 0 && xu + N <= W) {
        float4 cr = __ldg((const float4*)(r0 + xu));
        float4 cg = __ldg((const float4*)(r0 + HW + xu));
        float4 cb = __ldg((const float4*)(r0 + 2 * HW + xu));
        t[0] = quant3(cr.x, cg.x, cb.x);
        t[1] = quant3(cr.y, cg.y, cb.y);
        t[2] = quant3(cr.z, cg.z, cb.z);
        t[3] = quant3(cr.w, cg.w, cb.w);
        if (N == 5) {
            float er = __ldg(r0 + xu + 4);
            float eg = __ldg(r0 + HW + xu + 4);
            float eb = __ldg(r0 + 2 * HW + xu + 4);
            t[4] = quant3(er, eg, eb);
        }
    } else {
        #pragma unroll
        for (int i = 0; i < N; i++) {
            int x = xu + i;
            if (x >= 0 && x < W) {
                float r = __ldg(r0 + x);
                float g = __ldg(r0 + HW + x);
                float b = __ldg(r0 + 2 * HW + x);
                t[i] = quant3(r, g, b);
            } else t[i] = 0u;
        }
    }
}

__global__ __launch_bounds__(128) void packF_kernel(const float* __restrict__ hist) {
    int kxmin, kxmax, kymin, kymax;
    bbox_kxy(kxmin, kxmax, kymin, kymax);
    const int rx0 = kxmin - 3 + PAD, rx1 = kxmax + 4 + PAD;
    const int ry0 = kymin - 3 + PAD, ry1 = kymax + 4 + PAD;
    const int gx_lo = rx0 >> 2, gx_hi = rx1 >> 2;

    const int yp = blockIdx.y;
    if (yp < ry0 || yp > ry1) return;
    const int gb0 = blockIdx.x * 128;
    if (gb0 > gx_hi || gb0 + 127 < gx_lo) return;
    const int grp = gb0 + threadIdx.x;
    if (grp < gx_lo || grp > gx_hi) return;

    const int b = blockIdx.z;
    const int x0p = grp * 4;
    const int xu  = x0p - PAD;
    const int yu  = yp - PAD;

    const unsigned HW = (unsigned)(H * W);
    const float* hb = hist + (size_t)((unsigned)b * C) * HW;

    unsigned tc[4], tm[5], tp[5];
    qrow<4>(hb, xu, yu,     tc);
    qrow<5>(hb, xu, yu - 1, tm);
    qrow<5>(hb, xu, yu + 2, tp);

    const size_t rowlin = ((size_t)b * Hp + yp) * Wp;

    *(uint4*)(g_h4 + rowlin + x0p) = make_uint4(tc[0], tc[1], tc[2], tc[3]);
    #pragma unroll
    for (int c = 1; c < 4; c++) {
        unsigned* dst = g_h4 + (size_t)c * STRIDE + rowlin + x0p + c;
        dst[0] = tc[0]; dst[1] = tc[1]; dst[2] = tc[2]; dst[3] = tc[3];
    }

    uint4* Pd = g_P + rowlin + x0p;
    Pd[0] = make_uint4(tm[0], tm[1], tp[0], tp[1]);
    Pd[1] = make_uint4(tm[1], tm[2], tp[1], tp[2]);
    Pd[2] = make_uint4(tm[2], tm[3], tp[2], tp[3]);
    Pd[3] = make_uint4(tm[3], tm[4], tp[3], tp[4]);
}

// ---------------------------------------------------------------------------
// Main TAA kernel: 64x8 pixel tile per block, 16x4 threads, 4x2 px/thread.
//  - 3 uniform gather wavefronts/pixel (hard floor for a 48B footprint)
//  - pooling: vectorized LDS (LDS.128 + 2 scalars per row), vertical results
//    shared across 4 horizontal outputs, sliding-window horizontal combine
//  - float4 mv loads, float4 out stores
// ---------------------------------------------------------------------------
__global__ __launch_bounds__(64) void taa_kernel(const float* __restrict__ x_in,
                                                 const float* __restrict__ mv,
                                                 float* __restrict__ out) {
    __shared__ float s[3][10][72];

    const int tx = threadIdx.x;           // 0..15
    const int ty = threadIdx.y;           // 0..3
    const int bx0 = blockIdx.x * 64;
    const int by0 = blockIdx.y * 8;
    const int b = blockIdx.z;
    const int tid = ty * 16 + tx;         // 0..63

    const unsigned HW = (unsigned)(H * W);
    const float* xb = x_in + (size_t)((unsigned)b * C) * HW;

    // ---- Tile load (smem col c <-> gx = bx0-4+c on the fast path) --------
    const bool border = (bx0 == 0) | (bx0 + 64 == W) | (by0 == 0) | (by0 + 8 == H);
    if (!border) {
        const float4* src0 = (const float4*)(xb + (size_t)(by0 - 1) * W + (bx0 - 4));
        constexpr unsigned HW4 = (unsigned)(H * W / 4);
        constexpr unsigned W4  = (unsigned)(W / 4);
        #pragma unroll
        for (int k = 0; k < 9; k++) {
            int u = tid + k * 64;
            if (u < 540) {                      // 3 ch x 10 rows x 18 float4
                int c  = u / 180;
                int r  = u - c * 180;
                int ry = r / 18;
                int vx = r - ry * 18;
                float4 v = __ldg(src0 + (unsigned)c * HW4 + (unsigned)ry * W4 + vx);
                *(float4*)&s[c][ry][vx * 4] = v;
            }
        }
    } else {
        // Scalar clamp path: fill smem cols 3..69 (gx = bx0-1 .. bx0+65).
        for (int i = tid; i < 3 * 10 * 67; i += 64) {
            int c  = i / 670;
            int r  = i % 670;
            int ry = r / 67;
            int rx = r % 67;
            int gx = min(max(bx0 + rx - 1, 0), W - 1);
            int gy = min(max(by0 + ry - 1, 0), H - 1);
            s[c][ry][rx + 3] = __ldg(xb + (unsigned)c * HW + (unsigned)(gy * W + gx));
        }
    }
    __syncthreads();

    const int px0 = bx0 + 4 * tx;
    const int py0 = by0 + 2 * ty;
    const unsigned ubase = (unsigned)(b * Hp) * Wpu;
    constexpr unsigned STRIDEu = (unsigned)STRIDE;
    const float4* mvp = (const float4*)mv;

    float rep[2][4][3];                   // [row][col][channel]

    #pragma unroll
    for (int p = 0; p < 2; p++) {
        const int py = py0 + p;
        const unsigned moff = ((unsigned)b * HW + (unsigned)(py * W + px0)) >> 1;
        float4 mq0 = __ldg(mvp + moff);        // mv of px0, px0+1
        float4 mq1 = __ldg(mvp + moff + 1);    // mv of px0+2, px0+3

        #pragma unroll
        for (int h = 0; h < 4; h++) {
            const float gxv = (h == 0) ? mq0.x : (h == 1) ? mq0.z : (h == 2) ? mq1.x : mq1.z;
            const float gyv = (h == 0) ? mq0.y : (h == 1) ? mq0.w : (h == 2) ? mq1.y : mq1.w;

            // ---- Bicubic (5-tap Catmull-Rom) setup -----------------------
            float posx = (gxv + 1.0f) * 0.5f * (float)W;
            float posy = (gyv + 1.0f) * 0.5f * (float)H;
            float flx = floorf(posx - 0.5f);
            float fly = floorf(posy - 0.5f);
            float fxp = posx - (flx + 0.5f);
            float fyp = posy - (fly + 0.5f);

            int kx = (int)flx;
            int ky = (int)fly;
            kx = min(max(kx, -2), W - 1);
            ky = min(max(ky, -2), H - 1);

            float axm = fxp - 1.0f, aym = fyp - 1.0f;
            float fx2 = fxp * fxp,  fy2 = fyp * fyp;
            float w0x = -0.5f * fxp * (axm * axm);
            float w3x =  0.5f * fx2 * axm;
            float w12x = 1.0f - w0x - w3x;
            float w2x = ((-1.5f * fxp + 2.0f) * fxp + 0.5f) * fxp;
            float w0y = -0.5f * fyp * (aym * aym);
            float w3y =  0.5f * fy2 * aym;
            float w12y = 1.0f - w0y - w3y;
            float w2y = ((-1.5f * fyp + 2.0f) * fyp + 0.5f) * fyp;

            float fx = __fdividef(w2x, w12x);
            float fy = __fdividef(w2y, w12y);
            float gx0 = 1.0f - fx, gy0 = 1.0f - fy;

            float sk = w12x + w12y - w12x * w12y;
            float rdenom = __fdividef(1.0f, sk);

            float ax0 = w12x * gx0, ax1 = w12x * fx;
            float ay0 = w12y * gy0, ay1 = w12y * fy;
            float wA = ax0 * w0y,  wB = ax1 * w0y;    // row -1 : kx, kx+1
            float wC = ax0 * w3y,  wD = ax1 * w3y;    // row +2 : kx, kx+1
            float wE = w0x * ay0,  wF = w0x * ay1;    // col kx-1 : rows 0, +1
            float wG = w3x * ay0,  wH = w3x * ay1;    // col kx+2 : rows 0, +1
            float w00 = ax0 * ay0, w10 = ax1 * ay0;   // center 2x2
            float w01 = ax0 * ay1, w11 = ax1 * ay1;

            // ---- Gather: 3 uniform wavefronts ----------------------------
            const int kxp = kx + PAD;
            const int kyp = ky + PAD;
            const unsigned rowbase = ubase + (unsigned)kyp * Wpu;

            const int w = kxp - 1;
            const unsigned cq = (unsigned)((-w) & 3);
            const unsigned* baseq = g_h4 + (cq * STRIDEu + rowbase + (unsigned)w + cq);
            uint4 q0 = __ldg((const uint4*)baseq);           // t(kx-1..kx+2) @ ky
            uint4 q1 = __ldg((const uint4*)(baseq + Wpu));   // same @ ky+1

            uint4 pr = __ldg(g_P + (rowbase + (unsigned)kxp));
            // pr = { t[ky-1][kx], t[ky-1][kx+1], t[ky+2][kx], t[ky+2][kx+1] }

            // ---- Flattened weighted sum over 12 texels -------------------
            f3 acc = { 0.f, 0.f, 0.f };
            fma3(acc, dec(pr.x), wA);  fma3(acc, dec(pr.y), wB);
            fma3(acc, dec(pr.z), wC);  fma3(acc, dec(pr.w), wD);
            fma3(acc, dec(q0.x), wE);  fma3(acc, dec(q1.x), wF);
            fma3(acc, dec(q0.w), wG);  fma3(acc, dec(q1.w), wH);
            fma3(acc, dec(q0.y), w00); fma3(acc, dec(q0.z), w10);
            fma3(acc, dec(q1.y), w01); fma3(acc, dec(q1.z), w11);

            const float cxy = 2048.0f / 2047.0f;
            const float cz  = 1024.0f / 1023.0f;
            rep[p][h][0] = __saturatef(fmaf(acc.x, rdenom * cxy, -cxy));
            rep[p][h][1] = __saturatef(fmaf(acc.y, rdenom * cxy, -cxy));
            rep[p][h][2] = __saturatef(fmaf(acc.z, rdenom * cz,  -cz));
        }
    }

    // ---- Shared 3x3 min/max pooling for the 4x2 pixel strip --------------
    // Output rows use smem rows 2ty..2ty+3; cols 4tx+3..4tx+8 (window of 6).
    const int r0 = 2 * ty;
    const int t3 = 4 * tx + 3;
    const unsigned off0 = (unsigned)(b * C) * HW + (unsigned)(py0 * W + px0);

    #pragma unroll
    for (int c = 0; c < 3; c++) {
        // Load the 4x6 window: per row 1 scalar + 1 LDS.128 + 1 scalar.
        float rv[4][6];
        #pragma unroll
        for (int r = 0; r < 4; r++) {
            rv[r][0] = s[c][r0 + r][t3];
            float4 m = *(const float4*)&s[c][r0 + r][t3 + 1];   // cols 4tx+4..+7 (16B aligned)
            rv[r][1] = m.x; rv[r][2] = m.y; rv[r][3] = m.z; rv[r][4] = m.w;
            rv[r][5] = s[c][r0 + r][t3 + 5];
        }
        // Vertical: shared middle pair serves both output rows.
        float vx0[6], vx1[6], vn0[6], vn1[6];
        #pragma unroll
        for (int j = 0; j < 6; j++) {
            float amx = fmaxf(rv[1][j], rv[2][j]);
            float amn = fminf(rv[1][j], rv[2][j]);
            vx0[j] = fmaxf(amx, rv[0][j]);  vx1[j] = fmaxf(amx, rv[3][j]);
            vn0[j] = fminf(amn, rv[0][j]);  vn1[j] = fminf(amn, rv[3][j]);
        }
        // Horizontal sliding window of 3 over 6 -> 4 outputs per row/kind.
        float4 top, bot;
        {
            float MX[4], MN[4], MX1[4], MN1[4];
            #pragma unroll
            for (int j = 0; j < 4; j++) {
                MX[j]  = fmaxf(fmaxf(vx0[j], vx0[j + 1]), vx0[j + 2]);
                MN[j]  = fminf(fminf(vn0[j], vn0[j + 1]), vn0[j + 2]);
                MX1[j] = fmaxf(fmaxf(vx1[j], vx1[j + 1]), vx1[j + 2]);
                MN1[j] = fminf(fminf(vn1[j], vn1[j + 1]), vn1[j + 2]);
            }
            float t0 = fmaf(ALPHA, rv[1][1], (1.0f - ALPHA) * fminf(fmaxf(rep[0][0][c], MN[0]), MX[0]));
            float t1 = fmaf(ALPHA, rv[1][2], (1.0f - ALPHA) * fminf(fmaxf(rep[0][1][c], MN[1]), MX[1]));
            float t2 = fmaf(ALPHA, rv[1][3], (1.0f - ALPHA) * fminf(fmaxf(rep[0][2][c], MN[2]), MX[2]));
            float t3v = fmaf(ALPHA, rv[1][4], (1.0f - ALPHA) * fminf(fmaxf(rep[0][3][c], MN[3]), MX[3]));
            float b0 = fmaf(ALPHA, rv[2][1], (1.0f - ALPHA) * fminf(fmaxf(rep[1][0][c], MN1[0]), MX1[0]));
            float b1 = fmaf(ALPHA, rv[2][2], (1.0f - ALPHA) * fminf(fmaxf(rep[1][1][c], MN1[1]), MX1[1]));
            float b2 = fmaf(ALPHA, rv[2][3], (1.0f - ALPHA) * fminf(fmaxf(rep[1][2][c], MN1[2]), MX1[2]));
            float b3 = fmaf(ALPHA, rv[2][4], (1.0f - ALPHA) * fminf(fmaxf(rep[1][3][c], MN1[3]), MX1[3]));
            top = make_float4(t0, t1, t2, t3v);
            bot = make_float4(b0, b1, b2, b3);
        }
        *(float4*)(out + off0 + (unsigned)c * HW)               = top;
        *(float4*)(out + off0 + (unsigned)c * HW + (unsigned)W) = bot;
    }
}

// ---------------------------------------------------------------------------
extern "C" void kernel_launch(void* const* d_in, const int* in_sizes, int n_in,
                              void* d_out, int out_size) {
    const float* x    = (const float*)d_in[0];   // [B,C,H,W]
    const float* mv   = (const float*)d_in[1];   // [B,H,W,2]
    const float* hist = (const float*)d_in[2];   // [B,C,H,W]
    float* out = (float*)d_out;                  // [B,C,H,W]

    bbox_kernel<<<1800, 256>>>(mv);              // 1800*256*9 float4 = whole mv

    dim3 pf_grid(4, Hp, B);                      // 128 groups x 1 row per block
    packF_kernel<<<pf_grid, 128>>>(hist);

    dim3 blk(16, 4);
    dim3 grd(W / 64, H / 8, B);
    taa_kernel<<<grd, blk>>>(x, mv, out);
}

// round 17
// speedup vs baseline: 1.5733x; 1.5733x over previous
#include <cuda_runtime.h>
#include <math_constants.h>
#include <cstdint>

// Problem constants (fixed by setup_inputs).
constexpr int B = 4, C = 3, H = 1080, W = 1920;
constexpr int PAD = 8;                 // generous pad: window loads never go OOB
constexpr int Hp = H + 2 * PAD;        // 1096
constexpr int Wp = W + 2 * PAD;        // 1936 (divisible by 4)
constexpr float ALPHA = 0.1f;

constexpr size_t PLANE = (size_t)B * Hp * Wp;   // texel positions (padded)
constexpr unsigned Wpu = (unsigned)Wp;

// 4-phase shifted replicas (quad loads): texel lin of copy c lives at
// c*STRIDE + lin + c -> any 4-texel window is 16B-aligned in exactly one copy.
constexpr size_t STRIDE = PLANE + 32;           // slack for copy-shift overflow
__device__ __align__(16) unsigned g_h4[4 * STRIDE];

// Pair replica: P[y][x] = { t[y-1][x], t[y-1][x+1], t[y+2][x], t[y+2][x+1] }.
__device__ __align__(16) uint4 g_P[PLANE];

// mv bounding box, order-preserving-encoded {min x, max x, min y, max y}.
// Statically initialized; the atomic min/max fixpoint is identical across
// graph replays for identical mv, so no reset kernel is needed.
__device__ unsigned g_bbox[4] = { 0xFFFFFFFFu, 0u, 0xFFFFFFFFu, 0u };

struct f3 { float x, y, z; };

// Magic-number decode: (1 + r/2048, 1 + g/2048, 1 + b/1024); SHF+LOP3, no I2F.
__device__ __forceinline__ f3 dec(unsigned q) {
    unsigned r = ((q << 12) & 0x007FF000u) | 0x3F800000u;
    unsigned g = ((q << 1)  & 0x007FF000u) | 0x3F800000u;
    unsigned b = ((q >> 9)  & 0x007FE000u) | 0x3F800000u;
    return { __uint_as_float(r), __uint_as_float(g), __uint_as_float(b) };
}
__device__ __forceinline__ void fma3(f3& acc, const f3& v, float w) {
    acc.x = fmaf(v.x, w, acc.x);
    acc.y = fmaf(v.y, w, acc.y);
    acc.z = fmaf(v.z, w, acc.z);
}

// Order-preserving float <-> uint encoding (monotone increasing).
__device__ __forceinline__ unsigned enc_ord(float f) {
    unsigned u = __float_as_uint(f);
    return (u & 0x80000000u) ? ~u : (u | 0x80000000u);
}
__device__ __forceinline__ float dec_ord(unsigned e) {
    return __uint_as_float((e & 0x80000000u) ? (e ^ 0x80000000u) : ~e);
}

// Clamped tap-origin bbox from the mv float bbox (monotone map -> exact bound).
__device__ __forceinline__ void bbox_kxy(int& kxmin, int& kxmax, int& kymin, int& kymax) {
    float gx0 = dec_ord(g_bbox[0]), gx1 = dec_ord(g_bbox[1]);
    float gy0 = dec_ord(g_bbox[2]), gy1 = dec_ord(g_bbox[3]);
    kxmin = min(max((int)floorf((gx0 + 1.0f) * 0.5f * (float)W - 0.5f), -2), W - 1);
    kxmax = min(max((int)floorf((gx1 + 1.0f) * 0.5f * (float)W - 0.5f), -2), W - 1);
    kymin = min(max((int)floorf((gy0 + 1.0f) * 0.5f * (float)H - 0.5f), -2), H - 1);
    kymax = min(max((int)floorf((gy1 + 1.0f) * 0.5f * (float)H - 0.5f), -2), H - 1);
}

// ---------------------------------------------------------------------------
// bbox over mv: float4 = two (x,y) pairs. 900 blocks x 256 thr x 18 float4.
__global__ __launch_bounds__(256) void bbox_kernel(const float* __restrict__ mv) {
    const float4* m4 = (const float4*)mv;
    const unsigned base = blockIdx.x * 4608u + threadIdx.x;

    float mnx =  CUDART_INF_F, mxx = -CUDART_INF_F;
    float mny =  CUDART_INF_F, mxy = -CUDART_INF_F;
    #pragma unroll
    for (int k = 0; k < 18; k++) {
        float4 v = __ldg(m4 + base + k * 256u);
        mnx = fminf(mnx, fminf(v.x, v.z));  mxx = fmaxf(mxx, fmaxf(v.x, v.z));
        mny = fminf(mny, fminf(v.y, v.w));  mxy = fmaxf(mxy, fmaxf(v.y, v.w));
    }
    #pragma unroll
    for (int off = 16; off; off >>= 1) {
        mnx = fminf(mnx, __shfl_xor_sync(0xFFFFFFFFu, mnx, off));
        mxx = fmaxf(mxx, __shfl_xor_sync(0xFFFFFFFFu, mxx, off));
        mny = fminf(mny, __shfl_xor_sync(0xFFFFFFFFu, mny, off));
        mxy = fmaxf(mxy, __shfl_xor_sync(0xFFFFFFFFu, mxy, off));
    }
    __shared__ float s[4][8];
    int wid = threadIdx.x >> 5;
    if ((threadIdx.x & 31) == 0) {
        s[0][wid] = mnx; s[1][wid] = mxx; s[2][wid] = mny; s[3][wid] = mxy;
    }
    __syncthreads();
    if (threadIdx.x == 0) {
        #pragma unroll
        for (int wv = 1; wv < 8; wv++) {
            mnx = fminf(mnx, s[0][wv]);  mxx = fmaxf(mxx, s[1][wv]);
            mny = fminf(mny, s[2][wv]);  mxy = fmaxf(mxy, s[3][wv]);
        }
        atomicMin(&g_bbox[0], enc_ord(mnx));
        atomicMax(&g_bbox[1], enc_ord(mxx));
        atomicMin(&g_bbox[2], enc_ord(mny));
        atomicMax(&g_bbox[3], enc_ord(mxy));
    }
}

// ---------------------------------------------------------------------------
// packF: fused region pack (4 phase copies + pair replica), reads hist direct.
// ---------------------------------------------------------------------------
__device__ __forceinline__ unsigned quant3(float r, float g, float b) {
    return __float2uint_rn(r * 2047.0f)
         | (__float2uint_rn(g * 2047.0f) << 11)
         | (__float2uint_rn(b * 1023.0f) << 22);
}

template <int N>
__device__ __forceinline__ void qrow(const float* __restrict__ hb, int xu, int yu,
                                     unsigned* t) {
    if (yu < 0 || yu >= H) {
        #pragma unroll
        for (int i = 0; i < N; i++) t[i] = 0u;
        return;
    }
    const unsigned HW = (unsigned)(H * W);
    const float* r0 = hb + (unsigned)yu * (unsigned)W;
    if (xu >= 0 && xu + N <= W) {
        float4 cr = __ldg((const float4*)(r0 + xu));
        float4 cg = __ldg((const float4*)(r0 + HW + xu));
        float4 cb = __ldg((const float4*)(r0 + 2 * HW + xu));
        t[0] = quant3(cr.x, cg.x, cb.x);
        t[1] = quant3(cr.y, cg.y, cb.y);
        t[2] = quant3(cr.z, cg.z, cb.z);
        t[3] = quant3(cr.w, cg.w, cb.w);
        if (N == 5) {
            float er = __ldg(r0 + xu + 4);
            float eg = __ldg(r0 + HW + xu + 4);
            float eb = __ldg(r0 + 2 * HW + xu + 4);
            t[4] = quant3(er, eg, eb);
        }
    } else {
        #pragma unroll
        for (int i = 0; i < N; i++) {
            int x = xu + i;
            if (x >= 0 && x < W) {
                float r = __ldg(r0 + x);
                float g = __ldg(r0 + HW + x);
                float b = __ldg(r0 + 2 * HW + x);
                t[i] = quant3(r, g, b);
            } else t[i] = 0u;
        }
    }
}

__global__ __launch_bounds__(128) void packF_kernel(const float* __restrict__ hist) {
    int kxmin, kxmax, kymin, kymax;
    bbox_kxy(kxmin, kxmax, kymin, kymax);
    const int rx0 = kxmin - 3 + PAD, rx1 = kxmax + 4 + PAD;
    const int ry0 = kymin - 3 + PAD, ry1 = kymax + 4 + PAD;
    const int gx_lo = rx0 >> 2, gx_hi = rx1 >> 2;

    const int yp = blockIdx.y;
    if (yp < ry0 || yp > ry1) return;
    const int gb0 = blockIdx.x * 128;
    if (gb0 > gx_hi || gb0 + 127 < gx_lo) return;
    const int grp = gb0 + threadIdx.x;
    if (grp < gx_lo || grp > gx_hi) return;

    const int b = blockIdx.z;
    const int x0p = grp * 4;
    const int xu  = x0p - PAD;
    const int yu  = yp - PAD;

    const unsigned HW = (unsigned)(H * W);
    const float* hb = hist + (size_t)((unsigned)b * C) * HW;

    unsigned tc[4], tm[5], tp[5];
    qrow<4>(hb, xu, yu,     tc);
    qrow<5>(hb, xu, yu - 1, tm);
    qrow<5>(hb, xu, yu + 2, tp);

    const size_t rowlin = ((size_t)b * Hp + yp) * Wp;

    *(uint4*)(g_h4 + rowlin + x0p) = make_uint4(tc[0], tc[1], tc[2], tc[3]);
    #pragma unroll
    for (int c = 1; c < 4; c++) {
        unsigned* dst = g_h4 + (size_t)c * STRIDE + rowlin + x0p + c;
        dst[0] = tc[0]; dst[1] = tc[1]; dst[2] = tc[2]; dst[3] = tc[3];
    }

    uint4* Pd = g_P + rowlin + x0p;
    Pd[0] = make_uint4(tm[0], tm[1], tp[0], tp[1]);
    Pd[1] = make_uint4(tm[1], tm[2], tp[1], tp[2]);
    Pd[2] = make_uint4(tm[2], tm[3], tp[2], tp[3]);
    Pd[3] = make_uint4(tm[3], tm[4], tp[3], tp[4]);
}

// ---------------------------------------------------------------------------
// Main TAA kernel: 64x8 pixel tile per block, 32x4 threads, 2x2 px/thread.
//  - 3 uniform gather wavefronts/pixel (hard floor for a 48B footprint)
//  - 2x2 pooling sharing: 16 LDS + 36 FMNMX per 4 px per channel
//  - float4 mv loads (2 px/load), float2 out stores (2 px/store)
// ---------------------------------------------------------------------------
__global__ __launch_bounds__(128) void taa_kernel(const float* __restrict__ x_in,
                                                  const float* __restrict__ mv,
                                                  float* __restrict__ out) {
    __shared__ float s[3][10][72];

    const int tx = threadIdx.x;           // 0..31
    const int ty = threadIdx.y;           // 0..3
    const int bx0 = blockIdx.x * 64;
    const int by0 = blockIdx.y * 8;
    const int b = blockIdx.z;
    const int tid = ty * 32 + tx;         // 0..127

    const unsigned HW = (unsigned)(H * W);
    const float* xb = x_in + (size_t)((unsigned)b * C) * HW;

    // ---- Tile load (smem col c <-> gx = bx0-4+c on the fast path) --------
    const bool border = (bx0 == 0) | (bx0 + 64 == W) | (by0 == 0) | (by0 + 8 == H);
    if (!border) {
        const float4* src0 = (const float4*)(xb + (size_t)(by0 - 1) * W + (bx0 - 4));
        constexpr unsigned HW4 = (unsigned)(H * W / 4);
        constexpr unsigned W4  = (unsigned)(W / 4);
        #pragma unroll
        for (int k = 0; k < 5; k++) {
            int u = tid + k * 128;
            if (u < 540) {                      // 3 ch x 10 rows x 18 float4
                int c  = u / 180;
                int r  = u - c * 180;
                int ry = r / 18;
                int vx = r - ry * 18;
                float4 v = __ldg(src0 + (unsigned)c * HW4 + (unsigned)ry * W4 + vx);
                *(float4*)&s[c][ry][vx * 4] = v;
            }
        }
    } else {
        // Scalar clamp path: fill smem cols 3..69 (gx = bx0-1 .. bx0+65).
        #pragma unroll
        for (int k = 0; k < 16; k++) {
            int i = tid + k * 128;
            if (i < 3 * 10 * 67) {
                int c  = i / 670;
                int r  = i % 670;
                int ry = r / 67;
                int rx = r % 67;
                int gx = min(max(bx0 + rx - 1, 0), W - 1);
                int gy = min(max(by0 + ry - 1, 0), H - 1);
                s[c][ry][rx + 3] = __ldg(xb + (unsigned)c * HW + (unsigned)(gy * W + gx));
            }
        }
    }
    __syncthreads();

    const int px0 = bx0 + 2 * tx;
    const int py0 = by0 + 2 * ty;
    const unsigned ubase = (unsigned)(b * Hp) * Wpu;
    constexpr unsigned STRIDEu = (unsigned)STRIDE;
    const float4* mvp = (const float4*)mv;

    float rep[2][2][3];                   // [row][col][channel]

    #pragma unroll
    for (int p = 0; p < 2; p++) {
        const int py = py0 + p;
        // One float4 = mv of both horizontal pixels.
        float4 mq = __ldg(mvp + (((unsigned)b * HW + (unsigned)(py * W + px0)) >> 1));

        #pragma unroll
        for (int h = 0; h < 2; h++) {
            const float gxv = h ? mq.z : mq.x;
            const float gyv = h ? mq.w : mq.y;

            // ---- Bicubic (5-tap Catmull-Rom) setup -----------------------
            float posx = (gxv + 1.0f) * 0.5f * (float)W;
            float posy = (gyv + 1.0f) * 0.5f * (float)H;
            float flx = floorf(posx - 0.5f);
            float fly = floorf(posy - 0.5f);
            float fxp = posx - (flx + 0.5f);
            float fyp = posy - (fly + 0.5f);

            int kx = (int)flx;
            int ky = (int)fly;
            kx = min(max(kx, -2), W - 1);
            ky = min(max(ky, -2), H - 1);

            float axm = fxp - 1.0f, aym = fyp - 1.0f;
            float fx2 = fxp * fxp,  fy2 = fyp * fyp;
            float w0x = -0.5f * fxp * (axm * axm);
            float w3x =  0.5f * fx2 * axm;
            float w12x = 1.0f - w0x - w3x;
            float w2x = ((-1.5f * fxp + 2.0f) * fxp + 0.5f) * fxp;
            float w0y = -0.5f * fyp * (aym * aym);
            float w3y =  0.5f * fy2 * aym;
            float w12y = 1.0f - w0y - w3y;
            float w2y = ((-1.5f * fyp + 2.0f) * fyp + 0.5f) * fyp;

            float fx = __fdividef(w2x, w12x);
            float fy = __fdividef(w2y, w12y);
            float gx0 = 1.0f - fx, gy0 = 1.0f - fy;

            float sk = w12x + w12y - w12x * w12y;
            float rdenom = __fdividef(1.0f, sk);

            float ax0 = w12x * gx0, ax1 = w12x * fx;
            float ay0 = w12y * gy0, ay1 = w12y * fy;
            float wA = ax0 * w0y,  wB = ax1 * w0y;    // row -1 : kx, kx+1
            float wC = ax0 * w3y,  wD = ax1 * w3y;    // row +2 : kx, kx+1
            float wE = w0x * ay0,  wF = w0x * ay1;    // col kx-1 : rows 0, +1
            float wG = w3x * ay0,  wH = w3x * ay1;    // col kx+2 : rows 0, +1
            float w00 = ax0 * ay0, w10 = ax1 * ay0;   // center 2x2
            float w01 = ax0 * ay1, w11 = ax1 * ay1;

            // ---- Gather: 3 uniform wavefronts ----------------------------
            const int kxp = kx + PAD;
            const int kyp = ky + PAD;
            const unsigned rowbase = ubase + (unsigned)kyp * Wpu;

            const int w = kxp - 1;
            const unsigned cq = (unsigned)((-w) & 3);
            const unsigned* baseq = g_h4 + (cq * STRIDEu + rowbase + (unsigned)w + cq);
            uint4 q0 = __ldg((const uint4*)baseq);           // t(kx-1..kx+2) @ ky
            uint4 q1 = __ldg((const uint4*)(baseq + Wpu));   // same @ ky+1

            uint4 pr = __ldg(g_P + (rowbase + (unsigned)kxp));
            // pr = { t[ky-1][kx], t[ky-1][kx+1], t[ky+2][kx], t[ky+2][kx+1] }

            // ---- Flattened weighted sum over 12 texels -------------------
            f3 acc = { 0.f, 0.f, 0.f };
            fma3(acc, dec(pr.x), wA);  fma3(acc, dec(pr.y), wB);
            fma3(acc, dec(pr.z), wC);  fma3(acc, dec(pr.w), wD);
            fma3(acc, dec(q0.x), wE);  fma3(acc, dec(q1.x), wF);
            fma3(acc, dec(q0.w), wG);  fma3(acc, dec(q1.w), wH);
            fma3(acc, dec(q0.y), w00); fma3(acc, dec(q0.z), w10);
            fma3(acc, dec(q1.y), w01); fma3(acc, dec(q1.z), w11);

            const float cxy = 2048.0f / 2047.0f;
            const float cz  = 1024.0f / 1023.0f;
            rep[p][h][0] = __saturatef(fmaf(acc.x, rdenom * cxy, -cxy));
            rep[p][h][1] = __saturatef(fmaf(acc.y, rdenom * cxy, -cxy));
            rep[p][h][2] = __saturatef(fmaf(acc.z, rdenom * cz,  -cz));
        }
    }

    // ---- Shared 3x3 min/max pooling for the 2x2 pixel quad ---------------
    // Output rows use smem rows 2ty..2ty+3; cols use smem cols 2tx+3..2tx+6.
    const int r0 = 2 * ty;
    const int c0 = 2 * tx + 3;
    const unsigned off0 = (unsigned)(b * C) * HW + (unsigned)(py0 * W + px0);

    #pragma unroll
    for (int c = 0; c < 3; c++) {
        float vx0[4], vx1[4], vn0[4], vn1[4];
        float xTL, xTR, xBL, xBR;
        #pragma unroll
        for (int j = 0; j < 4; j++) {
            float m0 = s[c][r0    ][c0 + j];
            float m1 = s[c][r0 + 1][c0 + j];
            float m2 = s[c][r0 + 2][c0 + j];
            float m3 = s[c][r0 + 3][c0 + j];
            float amx = fmaxf(m1, m2), amn = fminf(m1, m2);
            vx0[j] = fmaxf(amx, m0);  vx1[j] = fmaxf(amx, m3);
            vn0[j] = fminf(amn, m0);  vn1[j] = fminf(amn, m3);
            if (j == 1) { xTL = m1; xBL = m2; }
            if (j == 2) { xTR = m1; xBR = m2; }
        }
        float mx0 = fmaxf(vx0[1], vx0[2]);
        float MXTL = fmaxf(mx0, vx0[0]), MXTR = fmaxf(mx0, vx0[3]);
        float mn0 = fminf(vn0[1], vn0[2]);
        float MNTL = fminf(mn0, vn0[0]), MNTR = fminf(mn0, vn0[3]);
        float mx1 = fmaxf(vx1[1], vx1[2]);
        float MXBL = fmaxf(mx1, vx1[0]), MXBR = fmaxf(mx1, vx1[3]);
        float mn1 = fminf(vn1[1], vn1[2]);
        float MNBL = fminf(mn1, vn1[0]), MNBR = fminf(mn1, vn1[3]);

        float rTL = fminf(fmaxf(rep[0][0][c], MNTL), MXTL);
        float rTR = fminf(fmaxf(rep[0][1][c], MNTR), MXTR);
        float rBL = fminf(fmaxf(rep[1][0][c], MNBL), MXBL);
        float rBR = fminf(fmaxf(rep[1][1][c], MNBR), MXBR);

        float2 top = make_float2(fmaf(ALPHA, xTL, (1.0f - ALPHA) * rTL),
                                 fmaf(ALPHA, xTR, (1.0f - ALPHA) * rTR));
        float2 bot = make_float2(fmaf(ALPHA, xBL, (1.0f - ALPHA) * rBL),
                                 fmaf(ALPHA, xBR, (1.0f - ALPHA) * rBR));
        *(float2*)(out + off0 + (unsigned)c * HW)               = top;
        *(float2*)(out + off0 + (unsigned)c * HW + (unsigned)W) = bot;
    }
}

// ---------------------------------------------------------------------------
extern "C" void kernel_launch(void* const* d_in, const int* in_sizes, int n_in,
                              void* d_out, int out_size) {
    const float* x    = (const float*)d_in[0];   // [B,C,H,W]
    const float* mv   = (const float*)d_in[1];   // [B,H,W,2]
    const float* hist = (const float*)d_in[2];   // [B,C,H,W]
    float* out = (float*)d_out;                  // [B,C,H,W]

    bbox_kernel<<<900, 256>>>(mv);               // 900*256*18 float4 = whole mv

    dim3 pf_grid(4, Hp, B);                      // 128 groups x 1 row per block
    packF_kernel<<<pf_grid, 128>>>(hist);

    dim3 blk(32, 4);
    dim3 grd(W / 64, H / 8, B);
    taa_kernel<<<grd, blk>>>(x, mv, out);
}